// round 2
// baseline (speedup 1.0000x reference)
#include <cuda_runtime.h>

// AttentionalPropagation: x [B=64, C=512, L=4096] fp32.
// Per l: q = x[:,:,l] (64x512); S = q q^T / sqrt(C); P = softmax(S); msg = P q;
// out = x + msg.
//
// R2 changes vs R1 baseline (1888us):
//  - fp32x2 packed FMA (fma.rn.f32x2) in both GEMM passes: halves FMA-pipe
//    instruction count (sm_103a dual-issue fp32 pipe).
//  - Double-buffered smem staging in both passes: chunk ch+1's global loads
//    are issued before computing chunk ch, hiding DRAM latency + STS drain
//    behind compute instead of serializing at each barrier.

namespace {

constexpr int kB  = 64;
constexpr int kC  = 512;
constexpr int kL  = 4096;
constexpr int LT  = 8;            // l-positions per CTA (8 x 4B = 32B sectors)
constexpr int CCH = 32;           // c per chunk
constexpr int NCH = kC / CCH;     // 16 chunks
constexpr int NT  = 512;          // threads per CTA

constexpr int P1_BUF = CCH * LT * kB;   // 16384 floats per pass-1 buffer

constexpr int XS2_PB = 33;              // pass-2 x buffer pitch over b (pad)
constexpr int XS2_PL = kB * XS2_PB;     // 2112 floats per l
constexpr int MB_P   = 259;             // msg transpose pitch (259%32=3, coprime)

// Pass-2 owns the high-water mark: 2 x-chunk buffers + mb.
constexpr int SMEM_FLOATS = 2 * LT * XS2_PL + kB * MB_P;  // 33792 + 16576 = 50368
constexpr int SMEM_BYTES  = SMEM_FLOATS * 4;              // 201472 B (< 227 KB)
static_assert(2 * P1_BUF <= 2 * LT * XS2_PL, "pass1 buffers fit in pass2 region");

typedef unsigned long long u64;

__device__ __forceinline__ u64 pk(float lo, float hi) {
    u64 r; asm("mov.b64 %0, {%1,%2};" : "=l"(r) : "f"(lo), "f"(hi)); return r;
}
__device__ __forceinline__ void upk(u64 v, float& lo, float& hi) {
    asm("mov.b64 {%0,%1}, %2;" : "=f"(lo), "=f"(hi) : "l"(v));
}
__device__ __forceinline__ u64 ffma2(u64 a, u64 b, u64 c) {
    u64 d; asm("fma.rn.f32x2 %0, %1, %2, %3;" : "=l"(d) : "l"(a), "l"(b), "l"(c));
    return d;
}

// Stage one c-chunk of x into pass-1 layout [cc][lt][b] (b fastest).
__device__ __forceinline__ void load_p1(const float* __restrict__ x, float* buf,
                                        int c0, int l0, int t) {
    #pragma unroll
    for (int k = 0; k < (kB * CCH) / NT; k++) {
        const int r  = t + k * NT;
        const int cl = r >> 6;
        const int b  = r & 63;
        const float* gp = x + ((size_t)(b * kC + (c0 + cl)) * kL + l0);
        const float4 v0 = *(const float4*)gp;
        const float4 v1 = *(const float4*)(gp + 4);
        float* sp = buf + cl * (LT * kB) + b;
        sp[0 * kB] = v0.x; sp[1 * kB] = v0.y; sp[2 * kB] = v0.z; sp[3 * kB] = v0.w;
        sp[4 * kB] = v1.x; sp[5 * kB] = v1.y; sp[6 * kB] = v1.z; sp[7 * kB] = v1.w;
    }
}

// Stage one c-chunk of x into pass-2 layout [lt][b][XS2_PB].
__device__ __forceinline__ void load_p2(const float* __restrict__ x, float* buf,
                                        int c0, int l0, int t) {
    #pragma unroll
    for (int k = 0; k < (kB * CCH) / NT; k++) {
        const int r  = t + k * NT;
        const int cl = r >> 6;
        const int b  = r & 63;
        const float* gp = x + ((size_t)(b * kC + (c0 + cl)) * kL + l0);
        const float4 v0 = *(const float4*)gp;
        const float4 v1 = *(const float4*)(gp + 4);
        float* sp = buf + b * XS2_PB + cl;
        sp[0 * XS2_PL] = v0.x; sp[1 * XS2_PL] = v0.y; sp[2 * XS2_PL] = v0.z; sp[3 * XS2_PL] = v0.w;
        sp[4 * XS2_PL] = v1.x; sp[5 * XS2_PL] = v1.y; sp[6 * XS2_PL] = v1.z; sp[7 * XS2_PL] = v1.w;
    }
}

__global__ void __launch_bounds__(NT, 1)
attn_prop_kernel(const float* __restrict__ x, float* __restrict__ out) {
    extern __shared__ float sm[];
    float* mb = sm + 2 * LT * XS2_PL;   // msg transpose buffer

    const int t  = threadIdx.x;
    const int l0 = blockIdx.x * LT;
    const int g  = t >> 6;           // l within tile (0..7)
    const int u  = t & 63;
    const int tn = u >> 3;           // n-tile (rows n = tn*8..+7)
    const int tm = u & 7;            // m-tile (cols m = tm*8..+7)

    // acc2[i][jj] = packed pair (S[i][2jj], S[i][2jj+1]) of the 8x8 tile.
    u64 acc2[8][4];
    #pragma unroll
    for (int i = 0; i < 8; i++)
        #pragma unroll
        for (int jj = 0; jj < 4; jj++) acc2[i][jj] = pk(0.0f, 0.0f);

    // ------------------------------ Pass 1: S = q q^T ------------------------
    load_p1(x, sm, 0, l0, t);
    __syncthreads();
    for (int ch = 0; ch < NCH; ch++) {
        if (ch + 1 < NCH)
            load_p1(x, sm + ((ch + 1) & 1) * P1_BUF, (ch + 1) * CCH, l0, t);
        const float* buf = sm + (ch & 1) * P1_BUF;
        #pragma unroll 2
        for (int cc = 0; cc < CCH; cc++) {
            const float* base = buf + cc * (LT * kB) + g * kB;
            const float4 a0 = *(const float4*)(base + tn * 8);
            const float4 a1 = *(const float4*)(base + tn * 8 + 4);
            const float4 b0 = *(const float4*)(base + tm * 8);
            const float4 b1 = *(const float4*)(base + tm * 8 + 4);
            const u64 qb2[4] = {pk(b0.x, b0.y), pk(b0.z, b0.w),
                                pk(b1.x, b1.y), pk(b1.z, b1.w)};
            const float qa[8] = {a0.x, a0.y, a0.z, a0.w, a1.x, a1.y, a1.z, a1.w};
            #pragma unroll
            for (int i = 0; i < 8; i++) {
                const u64 qa2 = pk(qa[i], qa[i]);
                #pragma unroll
                for (int jj = 0; jj < 4; jj++)
                    acc2[i][jj] = ffma2(qa2, qb2[jj], acc2[i][jj]);
            }
        }
        __syncthreads();
    }

    // ------------------------------ Softmax (registers + 8-lane shfl) --------
    const float inv_scale = 0.044194173824159216f;  // 1/sqrt(512)
    #pragma unroll
    for (int i = 0; i < 8; i++) {
        float v[8];
        #pragma unroll
        for (int jj = 0; jj < 4; jj++) upk(acc2[i][jj], v[2 * jj], v[2 * jj + 1]);
        float mx = -1e30f;
        #pragma unroll
        for (int j = 0; j < 8; j++) { v[j] *= inv_scale; mx = fmaxf(mx, v[j]); }
        mx = fmaxf(mx, __shfl_xor_sync(0xffffffffu, mx, 1));
        mx = fmaxf(mx, __shfl_xor_sync(0xffffffffu, mx, 2));
        mx = fmaxf(mx, __shfl_xor_sync(0xffffffffu, mx, 4));
        float s = 0.0f;
        #pragma unroll
        for (int j = 0; j < 8; j++) { v[j] = __expf(v[j] - mx); s += v[j]; }
        s += __shfl_xor_sync(0xffffffffu, s, 1);
        s += __shfl_xor_sync(0xffffffffu, s, 2);
        s += __shfl_xor_sync(0xffffffffu, s, 4);
        const float inv = 1.0f / s;
        #pragma unroll
        for (int j = 0; j < 8; j++) v[j] *= inv;
        #pragma unroll
        for (int jj = 0; jj < 4; jj++) acc2[i][jj] = pk(v[2 * jj], v[2 * jj + 1]);
    }

    // ------------------------------ Pass 2: out = x + P q --------------------
    load_p2(x, sm, 0, l0, t);   // prologue (pass-1 smem fully drained by loop-end sync)
    __syncthreads();
    for (int ch = 0; ch < NCH; ch++) {
        const int c0 = ch * CCH;
        if (ch + 1 < NCH)
            load_p2(x, sm + ((ch + 1) & 1) * (LT * XS2_PL), (ch + 1) * CCH, l0, t);
        const float* xbuf = sm + (ch & 1) * (LT * XS2_PL);

        // msg[n][c] = sum_m P[n][m] q[m][c]; each thread sums its 8 m's with
        // packed pairs, then 8-lane shfl reduction over tm.
        #pragma unroll 2
        for (int cc = 0; cc < CCH; cc++) {
            const float* qp = xbuf + g * XS2_PL + (tm * 8) * XS2_PB + cc;
            float qv[8];
            #pragma unroll
            for (int j = 0; j < 8; j++) qv[j] = qp[j * XS2_PB];
            const u64 qv2[4] = {pk(qv[0], qv[1]), pk(qv[2], qv[3]),
                                pk(qv[4], qv[5]), pk(qv[6], qv[7])};
            float part[8];
            #pragma unroll
            for (int i = 0; i < 8; i++) {
                u64 p2 = ffma2(acc2[i][0], qv2[0], pk(0.0f, 0.0f));
                p2 = ffma2(acc2[i][1], qv2[1], p2);
                p2 = ffma2(acc2[i][2], qv2[2], p2);
                p2 = ffma2(acc2[i][3], qv2[3], p2);
                float lo, hi; upk(p2, lo, hi);
                part[i] = lo + hi;
            }
            #pragma unroll
            for (int i = 0; i < 8; i++) {
                part[i] += __shfl_xor_sync(0xffffffffu, part[i], 1);
                part[i] += __shfl_xor_sync(0xffffffffu, part[i], 2);
                part[i] += __shfl_xor_sync(0xffffffffu, part[i], 4);
            }
            float myv = part[0];
            #pragma unroll
            for (int i = 1; i < 8; i++) if (tm == i) myv = part[i];
            mb[u * MB_P + cc * 8 + g] = myv;
        }
        __syncthreads();

        // out = x + msg, coalesced 32B sectors.
        #pragma unroll
        for (int k = 0; k < (kB * CCH) / NT; k++) {
            const int r  = t + k * NT;
            const int cl = r >> 6;
            const int b  = r & 63;
            const float* mp = mb   + b * MB_P  + cl * 8;
            const float* xp = xbuf + b * XS2_PB + cl;
            float4 o0, o1;
            o0.x = xp[0 * XS2_PL] + mp[0];
            o0.y = xp[1 * XS2_PL] + mp[1];
            o0.z = xp[2 * XS2_PL] + mp[2];
            o0.w = xp[3 * XS2_PL] + mp[3];
            o1.x = xp[4 * XS2_PL] + mp[4];
            o1.y = xp[5 * XS2_PL] + mp[5];
            o1.z = xp[6 * XS2_PL] + mp[6];
            o1.w = xp[7 * XS2_PL] + mp[7];
            float* gp = out + ((size_t)(b * kC + (c0 + cl)) * kL + l0);
            *(float4*)gp       = o0;
            *(float4*)(gp + 4) = o1;
        }
        __syncthreads();   // mb + xbuf drained before next chunk reuses them
    }
}

}  // namespace

extern "C" void kernel_launch(void* const* d_in, const int* in_sizes, int n_in,
                              void* d_out, int out_size) {
    (void)in_sizes; (void)n_in; (void)out_size;
    const float* x = (const float*)d_in[0];
    float* out     = (float*)d_out;

    cudaFuncSetAttribute(attn_prop_kernel,
                         cudaFuncAttributeMaxDynamicSharedMemorySize, SMEM_BYTES);

    attn_prop_kernel<<<kL / LT, NT, SMEM_BYTES>>>(x, out);
}